// round 3
// baseline (speedup 1.0000x reference)
#include <cuda_runtime.h>
#include <cuda_bf16.h>
#include <math.h>

#define WARPS_PER_BLOCK 8
#define MAX_BLOCKS 8192

__device__ float        g_partial[MAX_BLOCKS];
__device__ unsigned int g_count;   // atomicInc wraps back to 0 every run -> deterministic

__device__ __forceinline__ float log_sigmoid(float x) {
    return fminf(x, 0.0f) - log1pf(__expf(-fabsf(x)));
}

// One warp per batch element. All 22 row-gathers (float4/lane) are issued as
// independent loads buffered in registers BEFORE any accumulation, maximizing
// per-warp MLP. launch_bounds(256,2) grants ~128 regs so the full 20-row
// negative buffer (80 regs) stays register-resident.
__global__ void __launch_bounds__(256, 2)
skipgram_fused(const int* __restrict__ target,
               const int* __restrict__ context,
               const int* __restrict__ neg,
               const float4* __restrict__ emb4,
               float* __restrict__ out,
               int B, int K, int nblocks)
{
    const int lane = threadIdx.x & 31;
    const int wid  = threadIdx.x >> 5;
    const int b    = blockIdx.x * WARPS_PER_BLOCK + wid;

    __shared__ float s_red[WARPS_PER_BLOCK];
    __shared__ int   s_last;

    float result = 0.0f;
    if (b < B) {
        const int t = target[b];
        const int c = context[b];
        int my_neg = (lane < K && lane < 32) ? neg[b * K + lane] : 0;

        float4 v = __ldg(&emb4[(long long)t * 32 + lane]);
        float4 u = __ldg(&emb4[(long long)c * 32 + lane]);

        float4 s;
        if (K == 20) {
            // Hot path: issue ALL 20 loads first (register-buffered), sum after.
            float4 r[20];
            #pragma unroll
            for (int k = 0; k < 20; ++k) {
                int idx = __shfl_sync(0xffffffffu, my_neg, k);
                r[k] = __ldg(&emb4[(long long)idx * 32 + lane]);
            }
            s = r[0];
            #pragma unroll
            for (int k = 1; k < 20; ++k) {
                s.x += r[k].x; s.y += r[k].y; s.z += r[k].z; s.w += r[k].w;
            }
        } else {
            s = make_float4(0.f, 0.f, 0.f, 0.f);
            for (int k = 0; k < K; ++k) {
                int idx = (k < 32) ? __shfl_sync(0xffffffffu, my_neg, k)
                                   : neg[b * K + k];
                float4 r = __ldg(&emb4[(long long)idx * 32 + lane]);
                s.x += r.x; s.y += r.y; s.z += r.z; s.w += r.w;
            }
        }

        float pos_p = u.x * v.x + u.y * v.y + u.z * v.z + u.w * v.w;
        float neg_p = s.x * v.x + s.y * v.y + s.z * v.z + s.w * v.w;

        #pragma unroll
        for (int off = 16; off > 0; off >>= 1) {
            pos_p += __shfl_down_sync(0xffffffffu, pos_p, off);
            neg_p += __shfl_down_sync(0xffffffffu, neg_p, off);
        }
        if (lane == 0)
            result = log_sigmoid(pos_p) + log_sigmoid(-neg_p);
    }

    if (lane == 0) s_red[wid] = result;
    __syncthreads();

    if (threadIdx.x == 0) {
        float acc = 0.0f;
        #pragma unroll
        for (int w = 0; w < WARPS_PER_BLOCK; ++w) acc += s_red[w];
        g_partial[blockIdx.x] = acc;
        __threadfence();
        unsigned prev = atomicInc(&g_count, (unsigned)(nblocks - 1));
        s_last = (prev == (unsigned)(nblocks - 1)) ? 1 : 0;
    }
    __syncthreads();

    if (s_last) {
        __threadfence();
        float acc = 0.0f;
        for (int i = threadIdx.x; i < nblocks; i += 256)
            acc += g_partial[i];
        #pragma unroll
        for (int off = 16; off > 0; off >>= 1)
            acc += __shfl_down_sync(0xffffffffu, acc, off);
        if (lane == 0) s_red[wid] = acc;
        __syncthreads();
        if (threadIdx.x == 0) {
            float tot = 0.0f;
            #pragma unroll
            for (int w = 0; w < WARPS_PER_BLOCK; ++w) tot += s_red[w];
            out[0] = -tot / (float)B;
        }
    }
}

extern "C" void kernel_launch(void* const* d_in, const int* in_sizes, int n_in,
                              void* d_out, int out_size)
{
    const int*    target  = (const int*)d_in[0];
    const int*    context = (const int*)d_in[1];
    const int*    neg     = (const int*)d_in[2];
    const float4* emb4    = (const float4*)d_in[3];
    float*        out     = (float*)d_out;

    const int B = in_sizes[0];
    const int K = in_sizes[2] / B;   // 20
    const int nblocks = (B + WARPS_PER_BLOCK - 1) / WARPS_PER_BLOCK;  // 2048

    skipgram_fused<<<nblocks, 256>>>(target, context, neg, emb4, out, B, K, nblocks);
}